// round 9
// baseline (speedup 1.0000x reference)
#include <cuda_runtime.h>
#include <math_constants.h>
#include <stdint.h>

#define NB    8
#define NPTS  4096
#define KNN   20
#define CH    64
#define NSAMP (NB*NPTS*KNN)      // 655360
#define NQ    (NB*NPTS)          // 32768 queries
#define NSEG  2
#define SEGN  (NPTS/NSEG)        // 2048
#define BN_EPS 1e-5
#define SLOPE  0.2f
#define YPITCH 22

// ---------------- device scratch ----------------
__device__ float4 g_packed[NB*NPTS];                 // (x,y,z,|p|^2)
__device__ float4 g_E4[NSAMP];                       // edge diffs (d3, 0)
__device__ float  g_dl[NSEG*NQ*KNN];                 // per-segment sorted dists
__device__ double g_S1[6];
__device__ double g_S2[21];
__device__ float  g_W1f[CH*6];
__device__ float  g_c1[CH];
__device__ double g_h2sum[CH];
__device__ double g_h2sq[CH];
__device__ float  g_a2[CH], g_c2[CH];
__device__ float  g_hmax[(size_t)NQ*CH];
__device__ float  g_hmin[(size_t)NQ*CH];

// ---------------- packed f32x2 helpers ----------------
__device__ __forceinline__ unsigned long long fma2(unsigned long long a,
                                                   unsigned long long b,
                                                   unsigned long long c) {
    unsigned long long d;
    asm("fma.rn.f32x2 %0, %1, %2, %3;" : "=l"(d) : "l"(a), "l"(b), "l"(c));
    return d;
}
__device__ __forceinline__ unsigned long long pack2(float x) {
    unsigned long long d;
    asm("mov.b64 %0, {%1, %1};" : "=l"(d) : "f"(x));
    return d;
}
__device__ __forceinline__ void unpack2(unsigned long long v, float& lo, float& hi) {
    asm("mov.b64 {%0, %1}, %2;" : "=f"(lo), "=f"(hi) : "l"(v));
}

// ---------------- dummy (ncu lands on launch index 3 -> k1_emit) -------
__global__ void kdummy() {}

// ---------------- K0: pack points + zero accumulators ----------------
__global__ void k0_pack(const float* __restrict__ a) {
    int t = blockIdx.x*blockDim.x + threadIdx.x;     // 0..32767
    int b = t / NPTS, n = t % NPTS;
    const float* ab = a + (size_t)b*3*NPTS;
    float x = ab[n], y = ab[NPTS+n], z = ab[2*NPTS+n];
    float sq = fmaf(z,z, fmaf(y,y, x*x));
    g_packed[t] = make_float4(x,y,z,sq);
    if (blockIdx.x == 0) {
        int i = threadIdx.x;
        if (i < 6)  g_S1[i] = 0.0;
        if (i < 21) g_S2[i] = 0.0;
        if (i < CH) { g_h2sum[i] = 0.0; g_h2sq[i] = 0.0; }
    }
}

// ---------------- K1a: segmented distance-only top-20 ------------------
// d' = sq_j - 2*dot(p_i,p_j). Branchless sorted-insert network:
//   dl[t] = min(dl[t], max(d, dl[t-1]))   (exact, 2 FMNMX/slot, no preds)
__global__ void __launch_bounds__(128) k1_seg() {
    int blk = blockIdx.x;                            // 0..511
    int seg = (blk >= 256) ? 1 : 0;
    int qid = (blk & 255)*128 + threadIdx.x;         // 0..32767
    int b = qid / NPTS; int i = qid % NPTS;
    const float4* pts = &g_packed[b*NPTS];
    float4 pi = pts[i];
    float n2x = -2.f*pi.x, n2y = -2.f*pi.y, n2z = -2.f*pi.z;

    float dl[KNN];
    #pragma unroll
    for (int t = 0; t < KNN; t++) dl[t] = CUDART_INF_F;

    int jbase = seg * SEGN;
    for (int j = 0; j < SEGN; j += 8) {
        float dd[8];
        #pragma unroll
        for (int u = 0; u < 8; u++) {
            float4 pj = __ldg(&pts[jbase + j + u]);
            dd[u] = fmaf(n2z, pj.z, fmaf(n2y, pj.y, fmaf(n2x, pj.x, pj.w)));
        }
        #pragma unroll
        for (int u = 0; u < 8; u++) {
            float d = dd[u];
            if (d < dl[KNN-1]) {
                #pragma unroll
                for (int t = KNN-1; t >= 1; t--)
                    dl[t] = fminf(dl[t], fmaxf(d, dl[t-1]));
                dl[0] = fminf(dl[0], d);
            }
        }
    }
    size_t o = ((size_t)seg*NQ + qid)*KNN;
    #pragma unroll
    for (int t = 0; t < KNN; t++) g_dl[o+t] = dl[t];
}

// ---------------- K1b: warp-cooperative threshold rescan + emit --------
// One query per warp; ballot-compacted parallel emission of diff float4s.
// thr = exact 20th smallest (merged); identical fmaf chains make </==
// bitwise-sound. m strict hits + first (20-m) ties ascending-j = exact
// lex-(d,j) top-20 SET (k-order irrelevant downstream).
__global__ void __launch_bounds__(256) k1_emit() {
    __shared__ int ties[8][KNN];
    int wid  = threadIdx.x >> 5;
    int lane = threadIdx.x & 31;
    int qid  = blockIdx.x*8 + wid;                   // one query per warp
    int b = qid / NPTS; int i = qid % NPTS;
    const float4* pts = &g_packed[b*NPTS];
    float4 pi = pts[i];
    float n2x = -2.f*pi.x, n2y = -2.f*pi.y, n2z = -2.f*pi.z;

    float thr = 0.f;
    if (lane == 0) {
        const float* A = &g_dl[(size_t)qid*KNN];
        const float* B = &g_dl[((size_t)NQ + qid)*KNN];
        int ia = 0, ib = 0;
        float da = A[0], db = B[0];
        #pragma unroll
        for (int t = 0; t < KNN; t++) {
            bool ta = (da <= db);
            thr = ta ? da : db;
            if (ta) { ia++; da = (ia < KNN) ? A[ia] : CUDART_INF_F; }
            else    { ib++; db = (ib < KNN) ? B[ib] : CUDART_INF_F; }
        }
    }
    thr = __shfl_sync(~0u, thr, 0);

    float4* E = &g_E4[(size_t)qid*KNN];
    int m = 0, tcnt = 0;
    float4 pj = __ldg(&pts[lane]);                   // prefetch
    for (int it = 0; it < NPTS/32; it++) {
        float4 cur = pj;
        if (it < NPTS/32 - 1) pj = __ldg(&pts[(it+1)*32 + lane]);
        float d = fmaf(n2z, cur.z, fmaf(n2y, cur.y, fmaf(n2x, cur.x, cur.w)));
        unsigned lt = __ballot_sync(~0u, d <  thr);
        unsigned eq = __ballot_sync(~0u, d == thr);
        if (lt | eq) {
            unsigned below = (1u << lane) - 1u;
            if (d < thr)
                E[m + __popc(lt & below)] =
                    make_float4(cur.x-pi.x, cur.y-pi.y, cur.z-pi.z, 0.f);
            if (d == thr) {
                int pos = tcnt + __popc(eq & below);
                if (pos < KNN) ties[wid][pos] = it*32 + lane;
            }
            m    += __popc(lt);
            tcnt += __popc(eq);
        }
    }
    __syncwarp();
    int need = KNN - m;                              // >= 1, tcnt >= need
    if (lane < need) {
        float4 pt = pts[ties[wid][lane]];
        E[m + lane] = make_float4(pt.x-pi.x, pt.y-pi.y, pt.z-pi.z, 0.f);
    }
}

// ---------------- K2: 1st+2nd moments of edge features ----------------
// x = [diff3 (from E4), pts3 (from g_packed[qid])]
__global__ void k2_mom() {
    int t = blockIdx.x*blockDim.x + threadIdx.x;     // 512x256 -> 5 samples each
    float s1[6]; float s2[21];
    #pragma unroll
    for (int c = 0; c < 6; c++)  s1[c] = 0.f;
    #pragma unroll
    for (int q = 0; q < 21; q++) s2[q] = 0.f;

    #pragma unroll
    for (int s = 0; s < 5; s++) {
        int samp = t*5 + s;
        float4 v0 = g_E4[samp];
        float4 pt = g_packed[samp / KNN];
        float x[6] = {v0.x, v0.y, v0.z, pt.x, pt.y, pt.z};
        #pragma unroll
        for (int c = 0; c < 6; c++) s1[c] += x[c];
        int q = 0;
        #pragma unroll
        for (int c1 = 0; c1 < 6; c1++)
            #pragma unroll
            for (int c2 = c1; c2 < 6; c2++) { s2[q] = fmaf(x[c1], x[c2], s2[q]); q++; }
    }
    #pragma unroll
    for (int o = 16; o > 0; o >>= 1) {
        #pragma unroll
        for (int c = 0; c < 6; c++)  s1[c] += __shfl_xor_sync(~0u, s1[c], o);
        #pragma unroll
        for (int q = 0; q < 21; q++) s2[q] += __shfl_xor_sync(~0u, s2[q], o);
    }
    if ((threadIdx.x & 31) == 0) {
        #pragma unroll
        for (int c = 0; c < 6; c++)  atomicAdd(&g_S1[c], (double)s1[c]);
        #pragma unroll
        for (int q = 0; q < 21; q++) atomicAdd(&g_S2[q], (double)s2[q]);
    }
}

// ---------------- F1: fold BN1 into W1 ----------------
__global__ void f1_fold(const float* __restrict__ W1, const float* __restrict__ g1,
                        const float* __restrict__ b1) {
    int o = threadIdx.x; if (o >= CH) return;
    double M = (double)NSAMP;
    double m1[6];
    for (int c = 0; c < 6; c++) m1[c] = g_S1[c] / M;
    double E2[6][6]; int q = 0;
    for (int c1 = 0; c1 < 6; c1++)
        for (int c2 = c1; c2 < 6; c2++) { double v = g_S2[q++] / M; E2[c1][c2] = v; E2[c2][c1] = v; }
    double w[6];
    for (int c = 0; c < 6; c++) w[c] = (double)W1[o*6 + c];
    double mean = 0.0;
    for (int c = 0; c < 6; c++) mean += w[c]*m1[c];
    double e2 = 0.0;
    for (int c1 = 0; c1 < 6; c1++) { double acc = 0.0;
        for (int c2 = 0; c2 < 6; c2++) acc += w[c2]*E2[c1][c2];
        e2 += w[c1]*acc; }
    double var = e2 - mean*mean;
    double a = (double)g1[o] / sqrt(var + BN_EPS);
    g_c1[o] = (float)((double)b1[o] - mean*a);
    for (int c = 0; c < 6; c++) g_W1f[o*6 + c] = (float)(a*w[c]);
}

// ---------------- K3: fused MLP, warp-per-point phase B ----------------
// Phase A: thread (pa,ca) computes y1 for points pa, pa+4 (k-invariant
//   pts part folded into a per-point base -> 3 fma per k).
// Phase B: warp w owns point w; lane tile 4u x 10k; W2 pre-packed as
//   duplicated f32 pairs in smem (no pack MOVs in the hot loop).
#define PPB3 16
__global__ void __launch_bounds__(256) k3_mlp(const float* __restrict__ W2) {
    extern __shared__ float smem[];
    unsigned long long* sW2P = (unsigned long long*)smem;  // [c*64+u], 32KB
    float* y1s  = smem + 2*CH*CH;                          // [pw][c*22+k], 45KB
    float* ssum = y1s + 8*CH*YPITCH;
    float* ssq  = ssum + CH;

    int t = threadIdx.x;
    if (t < CH) { ssum[t] = 0.f; ssq[t] = 0.f; }
    for (int s = t; s < CH*CH; s += 256) {
        int u = s & 63, c = s >> 6;
        sW2P[c*CH + u] = pack2(W2[u*CH + c]);
    }
    // phase A identity
    int pa = t >> 6, ca = t & 63;
    float w1r[6];
    #pragma unroll
    for (int c = 0; c < 6; c++) w1r[c] = g_W1f[ca*6 + c];
    float c1v = g_c1[ca];
    // phase B identity
    int warp = t >> 5, lane = t & 31;
    int ug = lane & 15, kq = lane >> 4;
    int u0 = ug*4, k0 = kq*10;
    float su[4] = {0,0,0,0}, qu[4] = {0,0,0,0};
    __syncthreads();

    for (int ph = 0; ph < 2; ph++) {
        int pbase = blockIdx.x*PPB3 + ph*8;
        // ---- phase A ----
        #pragma unroll
        for (int pp = 0; pp < 2; pp++) {
            int pw = pa + pp*4;
            int p  = pbase + pw;
            float4 pt = g_packed[p];
            float base = c1v;
            base = fmaf(w1r[3], pt.x, base);
            base = fmaf(w1r[4], pt.y, base);
            base = fmaf(w1r[5], pt.z, base);
            const float4* Ep = &g_E4[(size_t)p*KNN];
            float* yo = &y1s[pw*CH*YPITCH + ca*YPITCH];
            #pragma unroll
            for (int k = 0; k < KNN; k++) {
                float4 v = Ep[k];
                float h = base;
                h = fmaf(w1r[0], v.x, h);
                h = fmaf(w1r[1], v.y, h);
                h = fmaf(w1r[2], v.z, h);
                yo[k] = (h >= 0.f) ? h : SLOPE*h;
            }
        }
        __syncthreads();
        // ---- phase B: warp-per-point, 4u x 10k per lane ----
        int p = pbase + warp;
        const float* yb = &y1s[warp*CH*YPITCH];
        unsigned long long acc[4][5];
        #pragma unroll
        for (int uu = 0; uu < 4; uu++)
            #pragma unroll
            for (int kk = 0; kk < 5; kk++) acc[uu][kk] = 0ull;
        #pragma unroll 4
        for (int c = 0; c < CH; c++) {
            const unsigned long long* wr = &sW2P[c*CH + u0];
            unsigned long long w0 = wr[0], w1 = wr[1], w2 = wr[2], w3 = wr[3];
            const float* yr = yb + c*YPITCH + k0;
            #pragma unroll
            for (int kk = 0; kk < 5; kk++) {
                unsigned long long yv = *(const unsigned long long*)(yr + 2*kk);
                acc[0][kk] = fma2(w0, yv, acc[0][kk]);
                acc[1][kk] = fma2(w1, yv, acc[1][kk]);
                acc[2][kk] = fma2(w2, yv, acc[2][kk]);
                acc[3][kk] = fma2(w3, yv, acc[3][kk]);
            }
        }
        float mx[4], mn[4];
        #pragma unroll
        for (int uu = 0; uu < 4; uu++) {
            mx[uu] = -CUDART_INF_F; mn[uu] = CUDART_INF_F;
            #pragma unroll
            for (int kk = 0; kk < 5; kk++) {
                float lo, hi;
                unpack2(acc[uu][kk], lo, hi);
                su[uu] += lo + hi;
                qu[uu] = fmaf(lo, lo, fmaf(hi, hi, qu[uu]));
                mx[uu] = fmaxf(mx[uu], fmaxf(lo, hi));
                mn[uu] = fminf(mn[uu], fminf(lo, hi));
            }
        }
        // combine kq halves (lane x with x+16)
        #pragma unroll
        for (int uu = 0; uu < 4; uu++) {
            mx[uu] = fmaxf(mx[uu], __shfl_down_sync(~0u, mx[uu], 16));
            mn[uu] = fminf(mn[uu], __shfl_down_sync(~0u, mn[uu], 16));
        }
        if (lane < 16) {
            *(float4*)&g_hmax[(size_t)p*CH + u0] = make_float4(mx[0],mx[1],mx[2],mx[3]);
            *(float4*)&g_hmin[(size_t)p*CH + u0] = make_float4(mn[0],mn[1],mn[2],mn[3]);
        }
        __syncthreads();                 // y1s reuse next ph
    }
    // BN2 stats: smem float atomics then global double atomics
    #pragma unroll
    for (int uu = 0; uu < 4; uu++) {
        atomicAdd(&ssum[u0+uu], su[uu]);
        atomicAdd(&ssq[u0+uu],  qu[uu]);
    }
    __syncthreads();
    if (t < CH) {
        atomicAdd(&g_h2sum[t], (double)ssum[t]);
        atomicAdd(&g_h2sq[t],  (double)ssq[t]);
    }
}

// ---------------- F2: finalize BN2 ----------------
__global__ void f2_fold(const float* __restrict__ g2, const float* __restrict__ b2) {
    int o = threadIdx.x; if (o >= CH) return;
    double M = (double)NSAMP;
    double m = g_h2sum[o] / M;
    double v = g_h2sq[o] / M - m*m;
    double a = (double)g2[o] / sqrt(v + BN_EPS);
    g_a2[o] = (float)a;
    g_c2[o] = (float)((double)b2[o] - m*a);
}

// ---------------- K5: BN2+lrelu via monotone max/min + transpose -------
__global__ void k5_out(float* __restrict__ out) {
    __shared__ float tile[32][33];
    int b = blockIdx.z;
    int n0 = blockIdx.x*32, o0 = blockIdx.y*32;
    int tx = threadIdx.x, ty = threadIdx.y;
    #pragma unroll
    for (int r = 0; r < 4; r++) {
        int n = n0 + ty + 8*r, o = o0 + tx;
        float a = g_a2[o], c = g_c2[o];
        size_t idx = ((size_t)(b*NPTS + n))*CH + o;
        float h = (a >= 0.f) ? g_hmax[idx] : g_hmin[idx];
        float v = fmaf(a, h, c);
        tile[ty + 8*r][tx] = (v >= 0.f) ? v : SLOPE*v;
    }
    __syncthreads();
    #pragma unroll
    for (int r = 0; r < 4; r++) {
        int o = o0 + ty + 8*r, n = n0 + tx;
        out[((size_t)(b*CH + o))*NPTS + n] = tile[tx][ty + 8*r];
    }
}

// ---------------- launch ----------------
extern "C" void kernel_launch(void* const* d_in, const int* in_sizes, int n_in,
                              void* d_out, int out_size) {
    const float* a  = (const float*)d_in[0];
    const float* W1 = (const float*)d_in[1];
    const float* g1 = (const float*)d_in[2];
    const float* b1 = (const float*)d_in[3];
    const float* W2 = (const float*)d_in[4];
    const float* g2 = (const float*)d_in[5];
    const float* b2 = (const float*)d_in[6];
    float* out = (float*)d_out;

    const int K3_SMEM = (2*CH*CH + 8*CH*YPITCH + 2*CH + 32) * 4;  // ~78.5KB
    cudaFuncSetAttribute(k3_mlp, cudaFuncAttributeMaxDynamicSharedMemorySize, K3_SMEM);

    // 1 dummy: ncu capture lands on launch index 3 == k1_emit
    kdummy<<<1, 32>>>();

    k0_pack<<<128, 256>>>(a);            // index 1
    k1_seg<<<512, 128>>>();              // index 2
    k1_emit<<<4096, 256>>>();            // index 3  <- profiled
    k2_mom<<<512, 256>>>();
    f1_fold<<<1, 64>>>(W1, g1, b1);
    k3_mlp<<<2048, 256, K3_SMEM>>>(W2);
    f2_fold<<<1, 64>>>(g2, b2);
    k5_out<<<dim3(128, 2, NB), dim3(32, 8)>>>(out);
}